// round 3
// baseline (speedup 1.0000x reference)
#include <cuda_runtime.h>
#include <cstdint>

// Problem constants (shapes fixed by the dataset)
#define NMAX 100000
#define EMAX 1600000
#define FIN  128
#define FOUT 40

// Scratch (static __device__ — no allocations allowed)
__device__ int   g_is64;
__device__ int   g_src32[EMAX];
__device__ int   g_dst32[EMAX];
__device__ float g_deg [NMAX];
__device__ float g_dinv[NMAX];
__device__ float g_h   [(size_t)NMAX * FIN];   // x @ W1
__device__ float g_a1  [(size_t)NMAX * FIN];   // aggregated layer-1 (pre-relu, pre-bias)
__device__ float g_h2  [(size_t)NMAX * FOUT];  // relu(a1+b1) @ W2

// ---------------------------------------------------------------------------
// edge-index dtype detection + normalization to int32
// ---------------------------------------------------------------------------
__global__ void k_flag_init() { g_is64 = 1; }

__global__ void k_detect(const long long* __restrict__ ei, int n, int count) {
    int i = blockIdx.x * blockDim.x + threadIdx.x;
    if (i < count) {
        long long v = ei[i];
        if (v < 0 || v >= (long long)n) atomicAnd(&g_is64, 0);
    }
}

__global__ void k_convert(const void* __restrict__ ei, int E) {
    int e = blockIdx.x * blockDim.x + threadIdx.x;
    if (e >= E) return;
    if (g_is64) {
        const long long* p = (const long long*)ei;
        g_src32[e] = (int)p[e];
        g_dst32[e] = (int)p[E + e];
    } else {
        const int* p = (const int*)ei;
        g_src32[e] = p[e];
        g_dst32[e] = p[E + e];
    }
}

// ---------------------------------------------------------------------------
// degree / normalization
// ---------------------------------------------------------------------------
__global__ void k_init_deg(int n) {
    int i = blockIdx.x * blockDim.x + threadIdx.x;
    if (i < n) g_deg[i] = 0.0f;
}

__global__ void k_accum_deg(int E) {
    int e = blockIdx.x * blockDim.x + threadIdx.x;
    if (e < E) atomicAdd(&g_deg[g_dst32[e]], 1.0f);
}

__global__ void k_dinv(int n) {
    int i = blockIdx.x * blockDim.x + threadIdx.x;
    if (i < n) g_dinv[i] = rsqrtf(g_deg[i] + 1.0f);  // +1 = self loop
}

// ---------------------------------------------------------------------------
// GEMM1: h = x @ W1   (N x 128 @ 128 x 128), plain fp32 FMA
// block = 256 threads, tile = 64 rows x 128 cols, K chunked by 32
// ---------------------------------------------------------------------------
__global__ void k_gemm1(const float* __restrict__ x, const float* __restrict__ W,
                        int n) {
    const int KC = 32;
    __shared__ float Ws[KC * FIN];   // 16 KB
    __shared__ float xs[64 * KC];    // 8 KB

    int t    = threadIdx.x;
    int lane = t & 31;
    int wy   = t >> 5;
    int row0 = blockIdx.x * 64;

    float4 acc[8];
#pragma unroll
    for (int i = 0; i < 8; i++) acc[i] = make_float4(0.f, 0.f, 0.f, 0.f);

    for (int kc = 0; kc < FIN; kc += KC) {
        for (int i = t; i < KC * FIN / 4; i += 256)
            ((float4*)Ws)[i] = ((const float4*)(W + (size_t)kc * FIN))[i];
        for (int i = t; i < 64 * KC / 4; i += 256) {
            int r  = i / (KC / 4);
            int k4 = i - r * (KC / 4);
            int gr = row0 + r;
            float4 v = make_float4(0.f, 0.f, 0.f, 0.f);
            if (gr < n) v = ((const float4*)(x + (size_t)gr * FIN + kc))[k4];
            ((float4*)xs)[i] = v;
        }
        __syncthreads();

#pragma unroll 4
        for (int kk = 0; kk < KC; kk++) {
            float4 w = ((const float4*)Ws)[kk * 32 + lane];
#pragma unroll
            for (int i = 0; i < 8; i++) {
                float xv = xs[(wy + 8 * i) * KC + kk];
                acc[i].x = fmaf(xv, w.x, acc[i].x);
                acc[i].y = fmaf(xv, w.y, acc[i].y);
                acc[i].z = fmaf(xv, w.z, acc[i].z);
                acc[i].w = fmaf(xv, w.w, acc[i].w);
            }
        }
        __syncthreads();
    }

#pragma unroll
    for (int i = 0; i < 8; i++) {
        int gr = row0 + wy + 8 * i;
        if (gr < n)
            ((float4*)(g_h + (size_t)gr * FIN))[lane] = acc[i];
    }
}

// ---------------------------------------------------------------------------
// a1 init with self-loop term: a1[i] = h[i] * dinv[i]^2
// ---------------------------------------------------------------------------
__global__ void k_selfloop1(int n) {
    int idx = blockIdx.x * blockDim.x + threadIdx.x;  // over n*32 float4s
    if (idx < n * (FIN / 4)) {
        int i = idx >> 5;
        float s = g_dinv[i]; s *= s;
        float4 v = ((const float4*)g_h)[idx];
        v.x *= s; v.y *= s; v.z *= s; v.w *= s;
        ((float4*)g_a1)[idx] = v;
    }
}

// ---------------------------------------------------------------------------
// scatter layer 1: a1[dst] += h[src] * dinv[src]*dinv[dst]   (warp per edge)
// ---------------------------------------------------------------------------
__global__ void k_scatter1(int E) {
    int w    = blockIdx.x * 8 + (threadIdx.x >> 5);
    int lane = threadIdx.x & 31;
    if (w >= E) return;
    int s = g_src32[w];
    int d = g_dst32[w];
    float norm = g_dinv[s] * g_dinv[d];
    float4 v = ((const float4*)(g_h + (size_t)s * FIN))[lane];
    float* o = g_a1 + (size_t)d * FIN + 4 * lane;
    atomicAdd(o + 0, v.x * norm);
    atomicAdd(o + 1, v.y * norm);
    atomicAdd(o + 2, v.z * norm);
    atomicAdd(o + 3, v.w * norm);
}

// ---------------------------------------------------------------------------
// GEMM2: h2 = relu(a1 + b1) @ W2   (N x 128 @ 128 x 40) — warp per node
// ---------------------------------------------------------------------------
__global__ void k_gemm2(const float* __restrict__ W2,
                        const float* __restrict__ b1, int n) {
    __shared__ float W2s[FIN * FOUT];  // 20 KB
    __shared__ float b1s[FIN];
    int t = threadIdx.x;
    for (int i = t; i < FIN * FOUT; i += 256) W2s[i] = W2[i];
    if (t < FIN) b1s[t] = b1[t];
    __syncthreads();

    int lane = t & 31;
    int node = blockIdx.x * 8 + (t >> 5);
    if (node >= n) return;

    float4 z  = ((const float4*)(g_a1 + (size_t)node * FIN))[lane];
    float4 bb = ((const float4*)b1s)[lane];
    z.x = fmaxf(z.x + bb.x, 0.f);
    z.y = fmaxf(z.y + bb.y, 0.f);
    z.z = fmaxf(z.z + bb.z, 0.f);
    z.w = fmaxf(z.w + bb.w, 0.f);

    float acc0 = 0.f, acc1 = 0.f;
#pragma unroll
    for (int c = 0; c < 4; c++) {
        float zc = (c == 0) ? z.x : (c == 1) ? z.y : (c == 2) ? z.z : z.w;
#pragma unroll
        for (int sl = 0; sl < 32; sl++) {
            float zk = __shfl_sync(0xffffffffu, zc, sl);
            int k = 4 * sl + c;   // z[k] lives in lane k/4, component k%4
            acc0 = fmaf(zk, W2s[k * FOUT + lane], acc0);
            if (lane < 8) acc1 = fmaf(zk, W2s[k * FOUT + 32 + lane], acc1);
        }
    }
    float* o = g_h2 + (size_t)node * FOUT;
    o[lane] = acc0;
    if (lane < 8) o[32 + lane] = acc1;
}

// ---------------------------------------------------------------------------
// out init with self-loop + bias: out[i][c] = h2[i][c]*dinv[i]^2 + b2[c]
// ---------------------------------------------------------------------------
__global__ void k_outinit(float* __restrict__ out, const float* __restrict__ b2,
                          int n) {
    int idx = blockIdx.x * blockDim.x + threadIdx.x;
    if (idx < n * FOUT) {
        int i = idx / FOUT;
        int c = idx - i * FOUT;
        float s = g_dinv[i];
        out[idx] = g_h2[idx] * s * s + b2[c];
    }
}

// ---------------------------------------------------------------------------
// scatter layer 2: out[dst] += h2[src] * norm   (warp per edge, 40 cols)
// ---------------------------------------------------------------------------
__global__ void k_scatter2(float* __restrict__ out, int E) {
    int w    = blockIdx.x * 8 + (threadIdx.x >> 5);
    int lane = threadIdx.x & 31;
    if (w >= E) return;
    int s = g_src32[w];
    int d = g_dst32[w];
    float norm = g_dinv[s] * g_dinv[d];
    const float* hp = g_h2 + (size_t)s * FOUT;
    float*       op = out  + (size_t)d * FOUT;
    atomicAdd(op + lane, hp[lane] * norm);
    if (lane < 8) atomicAdd(op + 32 + lane, hp[32 + lane] * norm);
}

// ---------------------------------------------------------------------------
extern "C" void kernel_launch(void* const* d_in, const int* in_sizes, int n_in,
                              void* d_out, int out_size) {
    const float* x   = (const float*)d_in[0];
    const void*  ei  = d_in[1];
    const float* W1  = (const float*)d_in[2];
    const float* b1  = (const float*)d_in[3];
    const float* W2  = (const float*)d_in[4];
    const float* b2  = (const float*)d_in[5];
    float*       out = (float*)d_out;

    int n = in_sizes[0] / FIN;
    if (n > NMAX) n = NMAX;
    int E = in_sizes[1] / 2;
    if (E > EMAX) E = EMAX;

    // normalize edge index to int32 (detect int64 vs int32 on device)
    int detect_cnt = 2048;
    if (detect_cnt > E) detect_cnt = E;
    k_flag_init<<<1, 1>>>();
    k_detect   <<<(detect_cnt + 255) / 256, 256>>>((const long long*)ei, n, detect_cnt);
    k_convert  <<<(E + 255) / 256, 256>>>(ei, E);

    k_init_deg <<<(n + 255) / 256, 256>>>(n);
    k_accum_deg<<<(E + 255) / 256, 256>>>(E);
    k_dinv     <<<(n + 255) / 256, 256>>>(n);

    k_gemm1    <<<(n + 63) / 64, 256>>>(x, W1, n);
    k_selfloop1<<<(n * (FIN / 4) + 255) / 256, 256>>>(n);
    k_scatter1 <<<(E + 7) / 8, 256>>>(E);

    k_gemm2    <<<(n + 7) / 8, 256>>>(W2, b1, n);
    k_outinit  <<<(n * FOUT + 255) / 256, 256>>>(out, b2, n);
    k_scatter2 <<<(E + 7) / 8, 256>>>(out, E);
}

// round 4
// speedup vs baseline: 1.6280x; 1.6280x over previous
#include <cuda_runtime.h>
#include <cstdint>

#define NMAX 100000
#define EMAX 1600000
#define FIN  128
#define FOUT 40

// Scratch (static __device__ — no allocations allowed)
__device__ int   g_is64;
__device__ int   g_src32 [EMAX];
__device__ int   g_dst32 [EMAX];
__device__ int   g_csr   [EMAX];        // src ids grouped by dst
__device__ int   g_degi  [NMAX];
__device__ int   g_fill  [NMAX];
__device__ int   g_rowptr[NMAX + 1];
__device__ float g_dinv[NMAX];
__device__ float g_h   [(size_t)NMAX * FIN];   // x @ W1
__device__ float g_a1  [(size_t)NMAX * FIN];   // relu(aggregated + b1)
__device__ float g_h2  [(size_t)NMAX * FOUT];  // a1 @ W2

// ---------------------------------------------------------------------------
// edge-index dtype detection + normalization to int32
// ---------------------------------------------------------------------------
__global__ void k_flag_init() { g_is64 = 1; }

__global__ void k_detect(const long long* __restrict__ ei, int n, int count) {
    int i = blockIdx.x * blockDim.x + threadIdx.x;
    if (i < count) {
        long long v = ei[i];
        if (v < 0 || v >= (long long)n) atomicAnd(&g_is64, 0);
    }
}

__global__ void k_convert(const void* __restrict__ ei, int E) {
    int e = blockIdx.x * blockDim.x + threadIdx.x;
    if (e >= E) return;
    if (g_is64) {
        const long long* p = (const long long*)ei;
        g_src32[e] = (int)p[e];
        g_dst32[e] = (int)p[E + e];
    } else {
        const int* p = (const int*)ei;
        g_src32[e] = p[e];
        g_dst32[e] = p[E + e];
    }
}

// ---------------------------------------------------------------------------
// CSR build: histogram -> scan -> fill
// ---------------------------------------------------------------------------
__global__ void k_zero_cnt(int n) {
    int i = blockIdx.x * blockDim.x + threadIdx.x;
    if (i < n) { g_degi[i] = 0; g_fill[i] = 0; }
}

__global__ void k_hist(int E) {
    int e = blockIdx.x * blockDim.x + threadIdx.x;
    if (e < E) atomicAdd(&g_degi[g_dst32[e]], 1);
}

// single-block Kogge-Stone scan, 1024 threads, chunked over n
__global__ void k_scan(int n) {
    __shared__ int sh[1024];
    __shared__ int carry_s;
    int tid = threadIdx.x;
    if (tid == 0) carry_s = 0;
    __syncthreads();
    for (int base = 0; base < n; base += 1024) {
        int i = base + tid;
        int v = (i < n) ? g_degi[i] : 0;
        sh[tid] = v;
        __syncthreads();
        for (int off = 1; off < 1024; off <<= 1) {
            int t = (tid >= off) ? sh[tid - off] : 0;
            __syncthreads();
            sh[tid] += t;
            __syncthreads();
        }
        int carry = carry_s;
        if (i < n) g_rowptr[i] = carry + sh[tid] - v;  // exclusive
        __syncthreads();
        if (tid == 1023) carry_s = carry + sh[1023];
        __syncthreads();
    }
    if (tid == 0) g_rowptr[n] = carry_s;
}

__global__ void k_dinv(int n) {
    int i = blockIdx.x * blockDim.x + threadIdx.x;
    if (i < n) g_dinv[i] = rsqrtf((float)g_degi[i] + 1.0f);  // +1 = self loop
}

__global__ void k_fill(int E) {
    int e = blockIdx.x * blockDim.x + threadIdx.x;
    if (e >= E) return;
    int d = g_dst32[e];
    int pos = g_rowptr[d] + atomicAdd(&g_fill[d], 1);
    g_csr[pos] = g_src32[e];
}

// ---------------------------------------------------------------------------
// GEMM1: h = x @ W1   (N x 128 @ 128 x 128), fp32 FMA
// ---------------------------------------------------------------------------
__global__ void k_gemm1(const float* __restrict__ x, const float* __restrict__ W,
                        int n) {
    const int KC = 32;
    __shared__ float Ws[KC * FIN];
    __shared__ float xs[64 * KC];

    int t    = threadIdx.x;
    int lane = t & 31;
    int wy   = t >> 5;
    int row0 = blockIdx.x * 64;

    float4 acc[8];
#pragma unroll
    for (int i = 0; i < 8; i++) acc[i] = make_float4(0.f, 0.f, 0.f, 0.f);

    for (int kc = 0; kc < FIN; kc += KC) {
        for (int i = t; i < KC * FIN / 4; i += 256)
            ((float4*)Ws)[i] = ((const float4*)(W + (size_t)kc * FIN))[i];
        for (int i = t; i < 64 * KC / 4; i += 256) {
            int r  = i / (KC / 4);
            int k4 = i - r * (KC / 4);
            int gr = row0 + r;
            float4 v = make_float4(0.f, 0.f, 0.f, 0.f);
            if (gr < n) v = ((const float4*)(x + (size_t)gr * FIN + kc))[k4];
            ((float4*)xs)[i] = v;
        }
        __syncthreads();

#pragma unroll 4
        for (int kk = 0; kk < KC; kk++) {
            float4 w = ((const float4*)Ws)[kk * 32 + lane];
#pragma unroll
            for (int i = 0; i < 8; i++) {
                float xv = xs[(wy + 8 * i) * KC + kk];
                acc[i].x = fmaf(xv, w.x, acc[i].x);
                acc[i].y = fmaf(xv, w.y, acc[i].y);
                acc[i].z = fmaf(xv, w.z, acc[i].z);
                acc[i].w = fmaf(xv, w.w, acc[i].w);
            }
        }
        __syncthreads();
    }

#pragma unroll
    for (int i = 0; i < 8; i++) {
        int gr = row0 + wy + 8 * i;
        if (gr < n)
            ((float4*)(g_h + (size_t)gr * FIN))[lane] = acc[i];
    }
}

// ---------------------------------------------------------------------------
// agg1 (pull): a1[d] = relu( sum_{s in N(d)} h[s]*dinv[s]*dinv[d]
//                            + h[d]*dinv[d]^2 + b1 )
// warp per node, lane holds float4 (4 cols)
// ---------------------------------------------------------------------------
__global__ void k_agg1(const float* __restrict__ b1, int n) {
    int node = blockIdx.x * 8 + (threadIdx.x >> 5);
    int lane = threadIdx.x & 31;
    if (node >= n) return;

    float di = g_dinv[node];
    float4 acc = ((const float4*)(g_h + (size_t)node * FIN))[lane];
    float s2 = di * di;
    acc.x *= s2; acc.y *= s2; acc.z *= s2; acc.w *= s2;

    int beg = g_rowptr[node], end = g_rowptr[node + 1];
    for (int k = beg; k < end; k++) {
        int s = g_csr[k];
        float w = g_dinv[s] * di;
        float4 v = ((const float4*)(g_h + (size_t)s * FIN))[lane];
        acc.x = fmaf(v.x, w, acc.x);
        acc.y = fmaf(v.y, w, acc.y);
        acc.z = fmaf(v.z, w, acc.z);
        acc.w = fmaf(v.w, w, acc.w);
    }

    float4 bb = ((const float4*)b1)[lane];
    acc.x = fmaxf(acc.x + bb.x, 0.f);
    acc.y = fmaxf(acc.y + bb.y, 0.f);
    acc.z = fmaxf(acc.z + bb.z, 0.f);
    acc.w = fmaxf(acc.w + bb.w, 0.f);
    ((float4*)(g_a1 + (size_t)node * FIN))[lane] = acc;
}

// ---------------------------------------------------------------------------
// GEMM2: h2 = a1 @ W2   (N x 128 @ 128 x 40) — warp per node
// ---------------------------------------------------------------------------
__global__ void k_gemm2(const float* __restrict__ W2, int n) {
    __shared__ float W2s[FIN * FOUT];
    int t = threadIdx.x;
    for (int i = t; i < FIN * FOUT; i += 256) W2s[i] = W2[i];
    __syncthreads();

    int lane = t & 31;
    int node = blockIdx.x * 8 + (t >> 5);
    if (node >= n) return;

    float4 z = ((const float4*)(g_a1 + (size_t)node * FIN))[lane];

    float acc0 = 0.f, acc1 = 0.f;
#pragma unroll
    for (int c = 0; c < 4; c++) {
        float zc = (c == 0) ? z.x : (c == 1) ? z.y : (c == 2) ? z.z : z.w;
#pragma unroll
        for (int sl = 0; sl < 32; sl++) {
            float zk = __shfl_sync(0xffffffffu, zc, sl);
            int k = 4 * sl + c;
            acc0 = fmaf(zk, W2s[k * FOUT + lane], acc0);
            if (lane < 8) acc1 = fmaf(zk, W2s[k * FOUT + 32 + lane], acc1);
        }
    }
    float* o = g_h2 + (size_t)node * FOUT;
    o[lane] = acc0;
    if (lane < 8) o[32 + lane] = acc1;
}

// ---------------------------------------------------------------------------
// agg2 (pull): out[d] = sum h2[s]*norm + h2[d]*dinv^2 + b2
// warp per node, lane covers col=lane and col=32+lane (lane<8)
// ---------------------------------------------------------------------------
__global__ void k_agg2(float* __restrict__ out, const float* __restrict__ b2,
                       int n) {
    int node = blockIdx.x * 8 + (threadIdx.x >> 5);
    int lane = threadIdx.x & 31;
    if (node >= n) return;

    float di = g_dinv[node];
    float s2 = di * di;
    const float* hp0 = g_h2 + (size_t)node * FOUT;
    float a0 = hp0[lane] * s2;
    float a1 = (lane < 8) ? hp0[32 + lane] * s2 : 0.f;

    int beg = g_rowptr[node], end = g_rowptr[node + 1];
    for (int k = beg; k < end; k++) {
        int s = g_csr[k];
        float w = g_dinv[s] * di;
        const float* hp = g_h2 + (size_t)s * FOUT;
        a0 = fmaf(hp[lane], w, a0);
        if (lane < 8) a1 = fmaf(hp[32 + lane], w, a1);
    }

    float* op = out + (size_t)node * FOUT;
    op[lane] = a0 + b2[lane];
    if (lane < 8) op[32 + lane] = a1 + b2[32 + lane];
}

// ---------------------------------------------------------------------------
extern "C" void kernel_launch(void* const* d_in, const int* in_sizes, int n_in,
                              void* d_out, int out_size) {
    const float* x   = (const float*)d_in[0];
    const void*  ei  = d_in[1];
    const float* W1  = (const float*)d_in[2];
    const float* b1  = (const float*)d_in[3];
    const float* W2  = (const float*)d_in[4];
    const float* b2  = (const float*)d_in[5];
    float*       out = (float*)d_out;

    int n = in_sizes[0] / FIN;
    if (n > NMAX) n = NMAX;
    int E = in_sizes[1] / 2;
    if (E > EMAX) E = EMAX;

    int detect_cnt = 2048;
    if (detect_cnt > E) detect_cnt = E;
    k_flag_init<<<1, 1>>>();
    k_detect   <<<(detect_cnt + 255) / 256, 256>>>((const long long*)ei, n, detect_cnt);
    k_convert  <<<(E + 255) / 256, 256>>>(ei, E);

    k_zero_cnt <<<(n + 255) / 256, 256>>>(n);
    k_hist     <<<(E + 255) / 256, 256>>>(E);
    k_scan     <<<1, 1024>>>(n);
    k_dinv     <<<(n + 255) / 256, 256>>>(n);
    k_fill     <<<(E + 255) / 256, 256>>>(E);

    k_gemm1    <<<(n + 63) / 64, 256>>>(x, W1, n);
    k_agg1     <<<(n + 7) / 8, 256>>>(b1, n);
    k_gemm2    <<<(n + 7) / 8, 256>>>(W2, n);
    k_agg2     <<<(n + 7) / 8, 256>>>(out, b2, n);
}

// round 5
// speedup vs baseline: 2.4612x; 1.5118x over previous
#include <cuda_runtime.h>
#include <cstdint>

#define NMAX 100000
#define EMAX 1600000
#define FIN  128
#define FOUT 40
#define SCAN_BLK 1024

// Scratch (static __device__ — no allocations allowed)
__device__ int   g_is64;
__device__ int   g_src32 [EMAX];
__device__ int   g_dst32 [EMAX];
__device__ int   g_csr   [EMAX];        // src ids grouped by dst
__device__ int   g_degi  [NMAX];
__device__ int   g_fill  [NMAX];
__device__ int   g_rowptr[NMAX + 1];
__device__ int   g_bsum  [(NMAX + SCAN_BLK - 1) / SCAN_BLK];
__device__ int   g_boff  [(NMAX + SCAN_BLK - 1) / SCAN_BLK];
__device__ float g_dinv[NMAX];
__device__ float g_h   [(size_t)NMAX * FIN];   // dinv * (x @ W1)
__device__ float g_h2  [(size_t)NMAX * FOUT];  // dinv * (a1 @ W2)

// ---------------------------------------------------------------------------
// edge-index dtype detection + normalization to int32
// ---------------------------------------------------------------------------
__global__ void k_flag_init() { g_is64 = 1; }

__global__ void k_detect(const long long* __restrict__ ei, int n, int count) {
    int i = blockIdx.x * blockDim.x + threadIdx.x;
    if (i < count) {
        long long v = ei[i];
        if (v < 0 || v >= (long long)n) atomicAnd(&g_is64, 0);
    }
}

__global__ void k_convert(const void* __restrict__ ei, int E) {
    int e = blockIdx.x * blockDim.x + threadIdx.x;
    if (e >= E) return;
    if (g_is64) {
        const long long* p = (const long long*)ei;
        g_src32[e] = (int)p[e];
        g_dst32[e] = (int)p[E + e];
    } else {
        const int* p = (const int*)ei;
        g_src32[e] = p[e];
        g_dst32[e] = p[E + e];
    }
}

// ---------------------------------------------------------------------------
// CSR build: histogram -> multi-block scan -> fill
// ---------------------------------------------------------------------------
__global__ void k_zero_cnt(int n) {
    int i = blockIdx.x * blockDim.x + threadIdx.x;
    if (i < n) { g_degi[i] = 0; g_fill[i] = 0; }
}

__global__ void k_hist(int E) {
    int e = blockIdx.x * blockDim.x + threadIdx.x;
    if (e < E) atomicAdd(&g_degi[g_dst32[e]], 1);
}

// scan phase A: per-block Kogge-Stone inclusive scan over SCAN_BLK slice,
// writes exclusive prefix to rowptr, block total to g_bsum, and dinv.
__global__ void k_scanA(int n) {
    __shared__ int sh[SCAN_BLK];
    int tid = threadIdx.x;
    int i = blockIdx.x * SCAN_BLK + tid;
    int v = (i < n) ? g_degi[i] : 0;
    if (i < n) g_dinv[i] = rsqrtf((float)v + 1.0f);  // +1 = self loop
    sh[tid] = v;
    __syncthreads();
    for (int off = 1; off < SCAN_BLK; off <<= 1) {
        int t = (tid >= off) ? sh[tid - off] : 0;
        __syncthreads();
        sh[tid] += t;
        __syncthreads();
    }
    if (i < n) g_rowptr[i] = sh[tid] - v;  // exclusive within block
    if (tid == SCAN_BLK - 1) g_bsum[blockIdx.x] = sh[tid];
}

// scan phase B: exclusive scan of block sums (single small block)
__global__ void k_scanB(int nblocks, int n, int E) {
    __shared__ int sh[256];
    int tid = threadIdx.x;
    int carry = 0;
    for (int base = 0; base < nblocks; base += 256) {
        int i = base + tid;
        int v = (i < nblocks) ? g_bsum[i] : 0;
        sh[tid] = v;
        __syncthreads();
        for (int off = 1; off < 256; off <<= 1) {
            int t = (tid >= off) ? sh[tid - off] : 0;
            __syncthreads();
            sh[tid] += t;
            __syncthreads();
        }
        if (i < nblocks) g_boff[i] = carry + sh[tid] - v;
        __syncthreads();
        carry += sh[255];
        __syncthreads();
    }
    if (tid == 0) g_rowptr[n] = E;
}

// scan phase C: add block offsets
__global__ void k_scanC(int n) {
    int i = blockIdx.x * blockDim.x + threadIdx.x;
    if (i < n) g_rowptr[i] += g_boff[i / SCAN_BLK];
}

__global__ void k_fill(int E) {
    int e = blockIdx.x * blockDim.x + threadIdx.x;
    if (e >= E) return;
    int d = g_dst32[e];
    int pos = g_rowptr[d] + atomicAdd(&g_fill[d], 1);
    g_csr[pos] = g_src32[e];
}

// ---------------------------------------------------------------------------
// GEMM1: h = dinv * (x @ W1)   (N x 128 @ 128 x 128), fp32 FMA
// ---------------------------------------------------------------------------
__global__ void k_gemm1(const float* __restrict__ x, const float* __restrict__ W,
                        int n) {
    const int KC = 32;
    __shared__ float Ws[KC * FIN];
    __shared__ float xs[64 * KC];

    int t    = threadIdx.x;
    int lane = t & 31;
    int wy   = t >> 5;
    int row0 = blockIdx.x * 64;

    float4 acc[8];
#pragma unroll
    for (int i = 0; i < 8; i++) acc[i] = make_float4(0.f, 0.f, 0.f, 0.f);

    for (int kc = 0; kc < FIN; kc += KC) {
        for (int i = t; i < KC * FIN / 4; i += 256)
            ((float4*)Ws)[i] = ((const float4*)(W + (size_t)kc * FIN))[i];
        for (int i = t; i < 64 * KC / 4; i += 256) {
            int r  = i / (KC / 4);
            int k4 = i - r * (KC / 4);
            int gr = row0 + r;
            float4 v = make_float4(0.f, 0.f, 0.f, 0.f);
            if (gr < n) v = ((const float4*)(x + (size_t)gr * FIN + kc))[k4];
            ((float4*)xs)[i] = v;
        }
        __syncthreads();

#pragma unroll 4
        for (int kk = 0; kk < KC; kk++) {
            float4 w = ((const float4*)Ws)[kk * 32 + lane];
#pragma unroll
            for (int i = 0; i < 8; i++) {
                float xv = xs[(wy + 8 * i) * KC + kk];
                acc[i].x = fmaf(xv, w.x, acc[i].x);
                acc[i].y = fmaf(xv, w.y, acc[i].y);
                acc[i].z = fmaf(xv, w.z, acc[i].z);
                acc[i].w = fmaf(xv, w.w, acc[i].w);
            }
        }
        __syncthreads();
    }

#pragma unroll
    for (int i = 0; i < 8; i++) {
        int gr = row0 + wy + 8 * i;
        if (gr < n) {
            float di = g_dinv[gr];
            float4 o = acc[i];
            o.x *= di; o.y *= di; o.z *= di; o.w *= di;
            ((float4*)(g_h + (size_t)gr * FIN))[lane] = o;
        }
    }
}

// ---------------------------------------------------------------------------
// fused agg1 + GEMM2:
//   z = relu( di * (sum_{s in N(d)} h[s] + h[d]) + b1 )   [h is pre-scaled]
//   h2[d] = di * (z @ W2)
// warp per node (8 warps/block), lane holds float4 of z
// ---------------------------------------------------------------------------
__global__ void k_agg1_gemm2(const float* __restrict__ b1,
                             const float* __restrict__ W2, int n) {
    __shared__ float W2s[FIN * FOUT];  // 20 KB
    __shared__ float b1s[FIN];
    int t = threadIdx.x;
    for (int i = t; i < FIN * FOUT; i += 256) W2s[i] = W2[i];
    if (t < FIN) b1s[t] = b1[t];
    __syncthreads();

    int node = blockIdx.x * 8 + (t >> 5);
    int lane = t & 31;
    if (node >= n) return;

    float di = g_dinv[node];
    float4 acc = ((const float4*)(g_h + (size_t)node * FIN))[lane];

    int beg = g_rowptr[node], end = g_rowptr[node + 1];
    for (int k = beg; k < end; k++) {
        int s = g_csr[k];
        float4 v = ((const float4*)(g_h + (size_t)s * FIN))[lane];
        acc.x += v.x; acc.y += v.y; acc.z += v.z; acc.w += v.w;
    }

    float4 bb = ((const float4*)b1s)[lane];
    float4 z;
    z.x = fmaxf(fmaf(acc.x, di, bb.x), 0.f);
    z.y = fmaxf(fmaf(acc.y, di, bb.y), 0.f);
    z.z = fmaxf(fmaf(acc.z, di, bb.z), 0.f);
    z.w = fmaxf(fmaf(acc.w, di, bb.w), 0.f);

    float acc0 = 0.f, acc1 = 0.f;
#pragma unroll
    for (int c = 0; c < 4; c++) {
        float zc = (c == 0) ? z.x : (c == 1) ? z.y : (c == 2) ? z.z : z.w;
#pragma unroll
        for (int sl = 0; sl < 32; sl++) {
            float zk = __shfl_sync(0xffffffffu, zc, sl);
            int k = 4 * sl + c;
            acc0 = fmaf(zk, W2s[k * FOUT + lane], acc0);
            if (lane < 8) acc1 = fmaf(zk, W2s[k * FOUT + 32 + lane], acc1);
        }
    }
    float* o = g_h2 + (size_t)node * FOUT;
    o[lane] = acc0 * di;
    if (lane < 8) o[32 + lane] = acc1 * di;
}

// ---------------------------------------------------------------------------
// agg2 (pull): out[d] = di * (sum h2[s] + h2[d]) + b2    [h2 pre-scaled]
// ---------------------------------------------------------------------------
__global__ void k_agg2(float* __restrict__ out, const float* __restrict__ b2,
                       int n) {
    int node = blockIdx.x * 8 + (threadIdx.x >> 5);
    int lane = threadIdx.x & 31;
    if (node >= n) return;

    float di = g_dinv[node];
    const float* hp0 = g_h2 + (size_t)node * FOUT;
    float a0 = hp0[lane];
    float a1 = (lane < 8) ? hp0[32 + lane] : 0.f;

    int beg = g_rowptr[node], end = g_rowptr[node + 1];
    for (int k = beg; k < end; k++) {
        int s = g_csr[k];
        const float* hp = g_h2 + (size_t)s * FOUT;
        a0 += hp[lane];
        if (lane < 8) a1 += hp[32 + lane];
    }

    float* op = out + (size_t)node * FOUT;
    op[lane] = fmaf(a0, di, b2[lane]);
    if (lane < 8) op[32 + lane] = fmaf(a1, di, b2[32 + lane]);
}

// ---------------------------------------------------------------------------
extern "C" void kernel_launch(void* const* d_in, const int* in_sizes, int n_in,
                              void* d_out, int out_size) {
    const float* x   = (const float*)d_in[0];
    const void*  ei  = d_in[1];
    const float* W1  = (const float*)d_in[2];
    const float* b1  = (const float*)d_in[3];
    const float* W2  = (const float*)d_in[4];
    const float* b2  = (const float*)d_in[5];
    float*       out = (float*)d_out;

    int n = in_sizes[0] / FIN;
    if (n > NMAX) n = NMAX;
    int E = in_sizes[1] / 2;
    if (E > EMAX) E = EMAX;

    int detect_cnt = 2048;
    if (detect_cnt > E) detect_cnt = E;
    k_flag_init<<<1, 1>>>();
    k_detect   <<<(detect_cnt + 255) / 256, 256>>>((const long long*)ei, n, detect_cnt);
    k_convert  <<<(E + 255) / 256, 256>>>(ei, E);

    int nsb = (n + SCAN_BLK - 1) / SCAN_BLK;
    k_zero_cnt <<<(n + 255) / 256, 256>>>(n);
    k_hist     <<<(E + 255) / 256, 256>>>(E);
    k_scanA    <<<nsb, SCAN_BLK>>>(n);
    k_scanB    <<<1, 256>>>(nsb, n, E);
    k_scanC    <<<(n + 255) / 256, 256>>>(n);
    k_fill     <<<(E + 255) / 256, 256>>>(E);

    k_gemm1    <<<(n + 63) / 64, 256>>>(x, W1, n);
    k_agg1_gemm2<<<(n + 7) / 8, 256>>>(b1, W2, n);
    k_agg2     <<<(n + 7) / 8, 256>>>(out, b2, n);
}